// round 9
// baseline (speedup 1.0000x reference)
#include <cuda_runtime.h>
#include <cuda_bf16.h>
#include <cstdint>

#define BATCH 8
#define CIN   32
#define COUT  64
#define HW    (512 * 512)
#define NPIX  (BATCH * HW)
#define TILE  128
#define NT    128

#define WPITCH 80            // W rows: 40 bf16 = 80B (B-frag LDS bank-perfect)
#define DPITCH 528           // x/D rows: 132 floats (bank = 4ch+px / 264o+px -> distinct)

// smem byte offsets
#define XD_OFF  0            // x: 32 rows * 528 = 16896 ; reused as D: 64 * 528 = 33792
#define WHI_OFF 33792        // 64 * 80 = 5120
#define WLO_OFF (WHI_OFF + 5120)
#define BS_OFF  (WLO_OFF + 5120)     // 256
#define MB_OFF  (BS_OFF + 256)       // 8
#define SMEM_TOT (MB_OFF + 16)       // 44320 < 48KB static

__device__ __forceinline__ void mma16816(float* c, const uint32_t* a, const uint32_t* b) {
    asm volatile(
        "mma.sync.aligned.m16n8k16.row.col.f32.bf16.bf16.f32 "
        "{%0,%1,%2,%3}, {%4,%5,%6,%7}, {%8,%9}, {%0,%1,%2,%3};"
        : "+f"(c[0]), "+f"(c[1]), "+f"(c[2]), "+f"(c[3])
        : "r"(a[0]), "r"(a[1]), "r"(a[2]), "r"(a[3]), "r"(b[0]), "r"(b[1]));
}

__device__ __forceinline__ uint32_t pack_bf16(__nv_bfloat16 e0, __nv_bfloat16 e1) {
    __nv_bfloat162 v; v.x = e0; v.y = e1;
    return *(uint32_t*)&v;
}
__device__ __forceinline__ uint32_t pack_hi(float a, float b) {
    return pack_bf16(__float2bfloat16(a), __float2bfloat16(b));
}
__device__ __forceinline__ uint32_t pack_lo(float a, float b) {
    __nv_bfloat16 ha = __float2bfloat16(a);
    __nv_bfloat16 hb = __float2bfloat16(b);
    return pack_bf16(__float2bfloat16(a - __bfloat162float(ha)),
                     __float2bfloat16(b - __bfloat162float(hb)));
}

static __device__ __forceinline__ uint32_t smem_u32(const void* p) {
    uint32_t a;
    asm("{ .reg .u64 t; cvta.to.shared.u64 t, %1; cvt.u32.u64 %0, t; }" : "=r"(a) : "l"(p));
    return a;
}

#define MBAR_INIT(mb, n) asm volatile("mbarrier.init.shared.b64 [%0], %1;" :: "r"(mb), "r"(n) : "memory")
#define MBAR_EXPECT(mb, by) asm volatile("mbarrier.arrive.expect_tx.shared.b64 _, [%0], %1;" :: "r"(mb), "r"(by) : "memory")
#define MBAR_WAIT(mb, ph) do {                                              \
    uint32_t _mb = (mb), _ph = (ph), _done;                                 \
    asm volatile("{ .reg .pred p; mbarrier.try_wait.parity.acquire.cta.shared::cta.b64 p, [%1], %2; selp.b32 %0,1,0,p; }" \
                 : "=r"(_done) : "r"(_mb), "r"(_ph) : "memory");            \
    if (!_done) {                                                            \
        asm volatile("{ .reg .pred P1; WL_%=: mbarrier.try_wait.parity.acquire.cta.shared::cta.b64 P1, [%0], %1, 0x989680; @P1 bra.uni WD_%=; bra.uni WL_%=; WD_%=: }" \
                     :: "r"(_mb), "r"(_ph) : "memory");                     \
    }                                                                        \
} while (0)

#define BULK_G2S(sdst, gsrc, by, mb) \
    asm volatile("cp.async.bulk.shared::cta.global.mbarrier::complete_tx::bytes [%0], [%1], %2, [%3];" \
                 :: "r"(sdst), "l"(gsrc), "r"(by), "r"(mb) : "memory")
#define BULK_S2G(gdst, ssrc, by) \
    asm volatile("cp.async.bulk.global.shared::cta.bulk_group [%0], [%1], %2;" \
                 :: "l"(gdst), "r"(ssrc), "r"(by) : "memory")

__global__ void __launch_bounds__(NT, 4)
spconv_mma_kernel(const float* __restrict__ x,
                  const float* __restrict__ Wg,
                  const float* __restrict__ bias,
                  float* __restrict__ out) {
    __shared__ __align__(16) char smc[SMEM_TOT];
    const uint32_t sb = smem_u32(smc);

    const int tid = threadIdx.x;
    const long long p0 = (long long)blockIdx.x * TILE;
    const int b   = (int)(p0 / HW);
    const int hw0 = (int)(p0 % HW);
    const float* xb = x + (long long)b * CIN * HW + hw0;

    // ---- mbarrier init, then x bulk-loads (32 rows x 512B) ----
    if (tid == 0) MBAR_INIT(sb + MB_OFF, 1);
    __syncthreads();
    if (tid == 0) {
        MBAR_EXPECT(sb + MB_OFF, CIN * TILE * 4);
        #pragma unroll
        for (int c = 0; c < CIN; ++c)
            BULK_G2S(sb + XD_OFF + c * DPITCH, xb + (long long)c * HW, TILE * 4, sb + MB_OFF);
    }

    // ---- stage W^T hi/lo (pitch 80B) + bias, overlapped with TMA ----
    {
        const int o    = tid >> 1;
        const int half = tid & 1;
        uint32_t hp[8], lp[8];
        #pragma unroll
        for (int j = 0; j < 8; ++j) {
            int ch = half * 16 + 2 * j;
            float w0 = Wg[ch * COUT + o];
            float w1 = Wg[(ch + 1) * COUT + o];
            hp[j] = pack_hi(w0, w1);
            lp[j] = pack_lo(w0, w1);
        }
        char* wh = smc + WHI_OFF + o * WPITCH + half * 32;
        char* wl = smc + WLO_OFF + o * WPITCH + half * 32;
        ((uint4*)wh)[0] = make_uint4(hp[0], hp[1], hp[2], hp[3]);
        ((uint4*)wh)[1] = make_uint4(hp[4], hp[5], hp[6], hp[7]);
        ((uint4*)wl)[0] = make_uint4(lp[0], lp[1], lp[2], lp[3]);
        ((uint4*)wl)[1] = make_uint4(lp[4], lp[5], lp[6], lp[7]);
    }
    if (tid < COUT) ((float*)(smc + BS_OFF))[tid] = bias[tid];

    const int w = tid >> 5;
    const int l = tid & 31;
    const int g = l >> 2;
    const int t = l & 3;
    const int rowbase = 32 * w;

    // ---- wait x, then conflict-free scalar LDS in fragment order ----
    MBAR_WAIT(sb + MB_OFF, 0);

    float v[4][8];   // r -> pixel rowbase+g+8r ; c -> channel 2t+dd[c]
    const char* xsm = smc + XD_OFF;
    #pragma unroll
    for (int r = 0; r < 4; ++r) {
        #pragma unroll
        for (int c = 0; c < 8; ++c) {
            const int dd = (c & 1) + ((c >> 1) & 1) * 8 + (c >> 2) * 16;  // 0,1,8,9,16,17,24,25
            const int ch = 2 * t + dd;
            v[r][c] = *(const float*)(xsm + ch * DPITCH + (rowbase + g + 8 * r) * 4);
        }
    }

    // ---- per-pixel activity via t-quad shfl OR ----
    uint32_t msk[4];
    #pragma unroll
    for (int r = 0; r < 4; ++r) {
        uint32_t m = 0u;
        #pragma unroll
        for (int c = 0; c < 8; ++c) m |= __float_as_uint(v[r][c]) & 0x7FFFFFFFu;
        m |= __shfl_xor_sync(0xFFFFFFFFu, m, 1);
        m |= __shfl_xor_sync(0xFFFFFFFFu, m, 2);
        msk[r] = m;
    }

    // ---- bf16 hi/lo fragments ----
    uint32_t ah[2][2][4], al[2][2][4];
    #pragma unroll
    for (int m = 0; m < 2; ++m) {
        #pragma unroll
        for (int k = 0; k < 2; ++k) {
            ah[m][k][0] = pack_hi(v[2*m][4*k],     v[2*m][4*k+1]);
            ah[m][k][1] = pack_hi(v[2*m+1][4*k],   v[2*m+1][4*k+1]);
            ah[m][k][2] = pack_hi(v[2*m][4*k+2],   v[2*m][4*k+3]);
            ah[m][k][3] = pack_hi(v[2*m+1][4*k+2], v[2*m+1][4*k+3]);
            al[m][k][0] = pack_lo(v[2*m][4*k],     v[2*m][4*k+1]);
            al[m][k][1] = pack_lo(v[2*m+1][4*k],   v[2*m+1][4*k+1]);
            al[m][k][2] = pack_lo(v[2*m][4*k+2],   v[2*m][4*k+3]);
            al[m][k][3] = pack_lo(v[2*m+1][4*k+2], v[2*m+1][4*k+3]);
        }
    }

    float acc[2][8][4];
    #pragma unroll
    for (int m = 0; m < 2; ++m)
        #pragma unroll
        for (int n = 0; n < 8; ++n)
            #pragma unroll
            for (int r = 0; r < 4; ++r) acc[m][n][r] = 0.0f;

    // all warps done reading x region; W smem ready
    __syncthreads();

    // ---- mainloop: 3-term bf16 split over K=32 ----
    const char* WH = smc + WHI_OFF;
    const char* WL = smc + WLO_OFF;
    #pragma unroll
    for (int k = 0; k < 2; ++k) {
        const int cb = 32 * k + 4 * t;
        #pragma unroll
        for (int nb = 0; nb < 2; ++nb) {
            uint32_t bh[4][2], bl[4][2];
            #pragma unroll
            for (int nn = 0; nn < 4; ++nn) {
                int o = 8 * (4 * nb + nn) + g;
                int off = o * WPITCH + cb;
                bh[nn][0] = *(const uint32_t*)(WH + off);
                bh[nn][1] = *(const uint32_t*)(WH + off + 16);
                bl[nn][0] = *(const uint32_t*)(WL + off);
                bl[nn][1] = *(const uint32_t*)(WL + off + 16);
            }
            #pragma unroll
            for (int nn = 0; nn < 4; ++nn)
                #pragma unroll
                for (int m = 0; m < 2; ++m)
                    mma16816(acc[m][4 * nb + nn], ah[m][k], bh[nn]);
            #pragma unroll
            for (int nn = 0; nn < 4; ++nn)
                #pragma unroll
                for (int m = 0; m < 2; ++m)
                    mma16816(acc[m][4 * nb + nn], ah[m][k], bl[nn]);
            #pragma unroll
            for (int nn = 0; nn < 4; ++nn)
                #pragma unroll
                for (int m = 0; m < 2; ++m)
                    mma16816(acc[m][4 * nb + nn], al[m][k], bh[nn]);
        }
    }

    // ---- epilogue: masked bias-add into smem D[o][px] (x region reused) ----
    const float* bs = (const float*)(smc + BS_OFF);
    char* Dt = smc + XD_OFF;
    #pragma unroll
    for (int m = 0; m < 2; ++m) {
        int px0 = rowbase + 16 * m + g;
        int px1 = px0 + 8;
        bool A0 = msk[2 * m]     != 0u;
        bool A1 = msk[2 * m + 1] != 0u;
        #pragma unroll
        for (int n = 0; n < 8; ++n) {
            int o = 8 * n + 2 * t;
            float2 bv = *(const float2*)(bs + o);
            *(float*)(Dt + o * DPITCH + px0 * 4)       = A0 ? acc[m][n][0] + bv.x : 0.0f;
            *(float*)(Dt + (o + 1) * DPITCH + px0 * 4) = A0 ? acc[m][n][1] + bv.y : 0.0f;
            *(float*)(Dt + o * DPITCH + px1 * 4)       = A1 ? acc[m][n][2] + bv.x : 0.0f;
            *(float*)(Dt + (o + 1) * DPITCH + px1 * 4) = A1 ? acc[m][n][3] + bv.y : 0.0f;
        }
    }

    asm volatile("fence.proxy.async.shared::cta;" ::: "memory");
    __syncthreads();

    // ---- bulk-store 64 output rows (512B each), no LSU wavefronts ----
    if (tid < COUT) {
        float* gdst = out + (long long)b * COUT * HW + (long long)tid * HW + hw0;
        BULK_S2G(gdst, sb + XD_OFF + tid * DPITCH, TILE * 4);
        asm volatile("cp.async.bulk.commit_group;" ::: "memory");
        asm volatile("cp.async.bulk.wait_group 0;" ::: "memory");
    }
}

extern "C" void kernel_launch(void* const* d_in, const int* in_sizes, int n_in,
                              void* d_out, int out_size) {
    const float* x  = (const float*)d_in[0];
    const float* Wg = (const float*)d_in[1];
    const float* bi = (const float*)d_in[2];
    float* out = (float*)d_out;

    const int grid = NPIX / TILE;   // 16384
    spconv_mma_kernel<<<grid, NT>>>(x, Wg, bi, out);
}